// round 6
// baseline (speedup 1.0000x reference)
#include <cuda_runtime.h>
#include <cuda_fp16.h>

// ---------------- problem constants ----------------
#define HH   256
#define H2   512
#define GG   64
#define NNODE 20000
#define NEDGE 320000

// ---------------- tile config ----------------------
#define TM      64
#define THREADS 256

#define ALD 260                          // fp32 words per A row (conflict-free frags)
#define HLD 516                          // fp16 elems per hidden row
#define WLD 136                          // fp32 words per weight-tile row (conflict-free B frags)
#define AS_BYTES (TM * ALD * 4)          // 66560
#define HS_BYTES (TM * HLD * 2)          // 66048
#define WBUF_BYTES (32 * WLD * 4)        // 17408
#define AS_OFF 0
#define HS_OFF (AS_OFF + AS_BYTES)
#define WS_OFF (HS_OFF + HS_BYTES)
#define B1_OFF (WS_OFF + 2 * WBUF_BYTES)
#define B2_OFF (B1_OFF + H2 * 4)
#define SMEM_BYTES (B2_OFF + HH * 4)     // 170496 < 227KB

// ---------------- device scratch (no cudaMalloc allowed) ----------------
// tf32-rounded weights: [node_w1, node_w2, glob_w1, glob_w2, edge_w1, edge_w2]
__device__ __align__(16) float g_wr[6 * 131072];
__device__ __align__(16) float g_gf[GG * HH];   // segment-mean global features

// ---------------- helpers ----------------
__device__ __forceinline__ unsigned t32(float x) {
    unsigned u;
    asm("cvt.rna.tf32.f32 %0, %1;" : "=r"(u) : "f"(x));
    return u;
}

__device__ __forceinline__ float gelu_tanh(float x) {
    // matches jax.nn.gelu(approximate=True)
    float t = tanhf(0.7978845608028654f * (x + 0.044715f * x * x * x));
    return 0.5f * x * (1.0f + t);
}

__device__ __forceinline__ void mma8(float* c, const unsigned* a, unsigned b0, unsigned b1) {
    asm volatile(
        "mma.sync.aligned.m16n8k8.row.col.f32.tf32.tf32.f32 "
        "{%0,%1,%2,%3}, {%4,%5,%6,%7}, {%8,%9}, {%0,%1,%2,%3};\n"
        : "+f"(c[0]), "+f"(c[1]), "+f"(c[2]), "+f"(c[3])
        : "r"(a[0]), "r"(a[1]), "r"(a[2]), "r"(a[3]), "r"(b0), "r"(b1));
}

#define CP_COMMIT asm volatile("cp.async.commit_group;\n")
#define CP_WAIT1  asm volatile("cp.async.wait_group 1;\n")
#define CP_WAIT0  asm volatile("cp.async.wait_group 0;\n")

// copy one [32 x 128] fp32 weight tile into smem buffer `buf`
__device__ __forceinline__ void copy_tile(char* smem, int buf, const float* __restrict__ gsrc,
                                          int ldw, int k0, int n0) {
    unsigned sb = (unsigned)__cvta_generic_to_shared(smem + WS_OFF + buf * WBUF_BYTES);
    int tid = threadIdx.x;
#pragma unroll
    for (int it = 0; it < 4; ++it) {
        int idx = tid + it * THREADS;          // 0..1023 vec4s
        int row = idx >> 5;                    // 0..31
        int cv  = idx & 31;                    // 0..31
        unsigned sa = sb + row * (WLD * 4) + cv * 16;
        const float* gp = gsrc + (size_t)(k0 + row) * ldw + n0 + cv * 4;
        asm volatile("cp.async.cg.shared.global [%0], [%1], 16;\n" ::"r"(sa), "l"(gp));
    }
}

// ---------------- prep: tf32-round all 6 weight matrices ----------------
__global__ void prep_kernel(const float* __restrict__ p0, const float* __restrict__ p1,
                            const float* __restrict__ p2, const float* __restrict__ p3,
                            const float* __restrict__ p4, const float* __restrict__ p5) {
    int i = blockIdx.x * blockDim.x + threadIdx.x;   // 786432 total
    int w = i >> 17;
    const float* src = (w == 0) ? p0 : (w == 1) ? p1 : (w == 2) ? p2
                      : (w == 3) ? p3 : (w == 4) ? p4 : p5;
    g_wr[i] = __uint_as_float(t32(src[i & 131071]));
}

// ---------------- segment mean (node_batch is sorted) ----------------
__global__ void seg_mean_kernel(const float* __restrict__ nf, const int* __restrict__ batch,
                                int n) {
    int gid = blockIdx.x;
    int lo, hi;
    { int a = 0, b = n; while (a < b) { int m = (a + b) >> 1; if (batch[m] <  gid) a = m + 1; else b = m; } lo = a; }
    { int a = lo, b = n; while (a < b) { int m = (a + b) >> 1; if (batch[m] <= gid) a = m + 1; else b = m; } hi = a; }
    int col = threadIdx.x;
    float s = 0.f;
    for (int r = lo; r < hi; ++r) s += nf[(size_t)r * HH + col];
    g_gf[gid * HH + col] = s / fmaxf((float)(hi - lo), 1.0f);
}

// ---------------- fused LN -> FFN -> residual ----------------
// out[r] = X[r] + W2^T gelu(W1^T LN(X[r]) + b1) + b2
__global__ void __launch_bounds__(THREADS, 1)
ffn_kernel(const float* __restrict__ Xp, long R,
           const float* __restrict__ gamma, const float* __restrict__ beta,
           int woff,
           const float* __restrict__ bias1, const float* __restrict__ bias2,
           float* __restrict__ out, int use_gf) {
    extern __shared__ char smem[];
    const float* X  = use_gf ? g_gf : Xp;
    const float* w1 = g_wr + woff;
    const float* w2 = g_wr + woff + 131072;

    unsigned* AsU = (unsigned*)(smem + AS_OFF);
    __half*   Hs  = (__half*)(smem + HS_OFF);
    float*    b1s = (float*)(smem + B1_OFF);
    float*    b2s = (float*)(smem + B2_OFF);

    int tid = threadIdx.x;
    int warp = tid >> 5, lane = tid & 31;
    int g = lane >> 2, tig = lane & 3;
    int wm = warp >> 2, wn = warp & 3;     // 2 m-warps x 4 n-warps
    int m0 = wm * 32;
    long base = (long)blockIdx.x * TM;

    for (int i = tid; i < H2; i += THREADS) b1s[i] = bias1[i];
    for (int i = tid; i < HH; i += THREADS) b2s[i] = bias2[i];

    // ---- LayerNorm: one warp per row-group of 8 rows, coalesced float4 ----
    float4 gm0 = *(const float4*)(gamma + lane * 4);
    float4 gm1 = *(const float4*)(gamma + 128 + lane * 4);
    float4 bt0 = *(const float4*)(beta + lane * 4);
    float4 bt1 = *(const float4*)(beta + 128 + lane * 4);
#pragma unroll
    for (int rr = 0; rr < 8; ++rr) {
        int row = warp * 8 + rr;
        long gr = base + row;
        float4 v0 = make_float4(0.f, 0.f, 0.f, 0.f);
        float4 v1 = make_float4(0.f, 0.f, 0.f, 0.f);
        if (gr < R) {
            v0 = *(const float4*)(X + gr * HH + lane * 4);
            v1 = *(const float4*)(X + gr * HH + 128 + lane * 4);
        }
        float s = v0.x + v0.y + v0.z + v0.w + v1.x + v1.y + v1.z + v1.w;
        float q = v0.x * v0.x + v0.y * v0.y + v0.z * v0.z + v0.w * v0.w
                + v1.x * v1.x + v1.y * v1.y + v1.z * v1.z + v1.w * v1.w;
#pragma unroll
        for (int o = 16; o; o >>= 1) {
            s += __shfl_xor_sync(0xFFFFFFFFu, s, o);
            q += __shfl_xor_sync(0xFFFFFFFFu, q, o);
        }
        float mean = s * (1.0f / HH);
        float var  = q * (1.0f / HH) - mean * mean;
        float rstd = rsqrtf(var + 1e-5f);
        unsigned* Ar = AsU + row * ALD;
        Ar[lane * 4 + 0] = t32((v0.x - mean) * rstd * gm0.x + bt0.x);
        Ar[lane * 4 + 1] = t32((v0.y - mean) * rstd * gm0.y + bt0.y);
        Ar[lane * 4 + 2] = t32((v0.z - mean) * rstd * gm0.z + bt0.z);
        Ar[lane * 4 + 3] = t32((v0.w - mean) * rstd * gm0.w + bt0.w);
        Ar[128 + lane * 4 + 0] = t32((v1.x - mean) * rstd * gm1.x + bt1.x);
        Ar[128 + lane * 4 + 1] = t32((v1.y - mean) * rstd * gm1.y + bt1.y);
        Ar[128 + lane * 4 + 2] = t32((v1.z - mean) * rstd * gm1.z + bt1.z);
        Ar[128 + lane * 4 + 3] = t32((v1.w - mean) * rstd * gm1.w + bt1.w);
    }
    __syncthreads();

    float acc[2][4][4];

    // ================= GEMM1: H1[64,512] = As[64,256] @ w1[256,512], GELU -> Hs =================
#pragma unroll 1
    for (int nc = 0; nc < 4; ++nc) {
#pragma unroll
        for (int mt = 0; mt < 2; ++mt)
#pragma unroll
            for (int nt = 0; nt < 4; ++nt)
#pragma unroll
                for (int i = 0; i < 4; ++i) acc[mt][nt][i] = 0.f;
        int n0g = nc * 128;
        copy_tile(smem, 0, w1, H2, 0, n0g);
        CP_COMMIT;
#pragma unroll 1
        for (int kt = 0; kt < 8; ++kt) {
            int cur = kt & 1;
            if (kt + 1 < 8) {
                copy_tile(smem, cur ^ 1, w1, H2, (kt + 1) * 32, n0g);
                CP_COMMIT;
                CP_WAIT1;
            } else {
                CP_WAIT0;
            }
            __syncthreads();
            const unsigned* Ws = (const unsigned*)(smem + WS_OFF + cur * WBUF_BYTES);
#pragma unroll
            for (int ks = 0; ks < 4; ++ks) {
                int k = kt * 32 + ks * 8;
                unsigned a[2][4];
#pragma unroll
                for (int mt = 0; mt < 2; ++mt) {
                    int r = m0 + mt * 16 + g;
                    a[mt][0] = AsU[r * ALD + k + tig];
                    a[mt][1] = AsU[(r + 8) * ALD + k + tig];
                    a[mt][2] = AsU[r * ALD + k + tig + 4];
                    a[mt][3] = AsU[(r + 8) * ALD + k + tig + 4];
                }
#pragma unroll
                for (int nt = 0; nt < 4; ++nt) {
                    int c = wn * 32 + nt * 8 + g;
                    unsigned b0 = Ws[(ks * 8 + tig) * WLD + c];
                    unsigned b1 = Ws[(ks * 8 + tig + 4) * WLD + c];
                    mma8(acc[0][nt], a[0], b0, b1);
                    mma8(acc[1][nt], a[1], b0, b1);
                }
            }
            __syncthreads();
        }
        // epilogue: bias + GELU -> Hs (fp16)
#pragma unroll
        for (int mt = 0; mt < 2; ++mt) {
            int r = m0 + mt * 16 + g;
#pragma unroll
            for (int nt = 0; nt < 4; ++nt) {
                int col = n0g + wn * 32 + nt * 8 + 2 * tig;
                float h0 = gelu_tanh(acc[mt][nt][0] + b1s[col]);
                float h1 = gelu_tanh(acc[mt][nt][1] + b1s[col + 1]);
                float h2 = gelu_tanh(acc[mt][nt][2] + b1s[col]);
                float h3 = gelu_tanh(acc[mt][nt][3] + b1s[col + 1]);
                *(__half2*)(Hs + (size_t)r * HLD + col)       = __floats2half2_rn(h0, h1);
                *(__half2*)(Hs + (size_t)(r + 8) * HLD + col) = __floats2half2_rn(h2, h3);
            }
        }
    }
    __syncthreads();

    // ================= GEMM2: O[64,256] = Hs[64,512] @ w2[512,256] + b2 + X =================
#pragma unroll 1
    for (int nc = 0; nc < 2; ++nc) {
#pragma unroll
        for (int mt = 0; mt < 2; ++mt)
#pragma unroll
            for (int nt = 0; nt < 4; ++nt)
#pragma unroll
                for (int i = 0; i < 4; ++i) acc[mt][nt][i] = 0.f;
        int n0g = nc * 128;
        copy_tile(smem, 0, w2, HH, 0, n0g);
        CP_COMMIT;
#pragma unroll 1
        for (int kt = 0; kt < 16; ++kt) {
            int cur = kt & 1;
            if (kt + 1 < 16) {
                copy_tile(smem, cur ^ 1, w2, HH, (kt + 1) * 32, n0g);
                CP_COMMIT;
                CP_WAIT1;
            } else {
                CP_WAIT0;
            }
            __syncthreads();
            const unsigned* Ws = (const unsigned*)(smem + WS_OFF + cur * WBUF_BYTES);
#pragma unroll
            for (int ks = 0; ks < 4; ++ks) {
                int k = kt * 32 + ks * 8;
                unsigned a[2][4];
#pragma unroll
                for (int mt = 0; mt < 2; ++mt) {
                    int r = m0 + mt * 16 + g;
                    a[mt][0] = t32(__half2float(Hs[(size_t)r * HLD + k + tig]));
                    a[mt][1] = t32(__half2float(Hs[(size_t)(r + 8) * HLD + k + tig]));
                    a[mt][2] = t32(__half2float(Hs[(size_t)r * HLD + k + tig + 4]));
                    a[mt][3] = t32(__half2float(Hs[(size_t)(r + 8) * HLD + k + tig + 4]));
                }
#pragma unroll
                for (int nt = 0; nt < 4; ++nt) {
                    int c = wn * 32 + nt * 8 + g;
                    unsigned b0 = Ws[(ks * 8 + tig) * WLD + c];
                    unsigned b1 = Ws[(ks * 8 + tig + 4) * WLD + c];
                    mma8(acc[0][nt], a[0], b0, b1);
                    mma8(acc[1][nt], a[1], b0, b1);
                }
            }
            __syncthreads();
        }
        // epilogue: bias + residual, store float2
#pragma unroll
        for (int mt = 0; mt < 2; ++mt) {
            int r = m0 + mt * 16 + g;
            long gr0 = base + r;
            long gr1 = gr0 + 8;
#pragma unroll
            for (int nt = 0; nt < 4; ++nt) {
                int col = n0g + wn * 32 + nt * 8 + 2 * tig;
                if (gr0 < R) {
                    float2 x = *(const float2*)(X + gr0 * HH + col);
                    float2 o = make_float2(acc[mt][nt][0] + b2s[col] + x.x,
                                           acc[mt][nt][1] + b2s[col + 1] + x.y);
                    *(float2*)(out + gr0 * HH + col) = o;
                }
                if (gr1 < R) {
                    float2 x = *(const float2*)(X + gr1 * HH + col);
                    float2 o = make_float2(acc[mt][nt][2] + b2s[col] + x.x,
                                           acc[mt][nt][3] + b2s[col + 1] + x.y);
                    *(float2*)(out + gr1 * HH + col) = o;
                }
            }
        }
    }
}

// ---------------- launch ----------------
extern "C" void kernel_launch(void* const* d_in, const int* in_sizes, int n_in,
                              void* d_out, int out_size) {
    const float* nodef = (const float*)d_in[0];
    const float* edgef = (const float*)d_in[1];
    const int*   batch = (const int*)d_in[2];
    // 18 param arrays at the tail: 3 groups x [norm_g, norm_b, w1, b1, w2, b2]
    int pb = n_in - 18;
    const float* P[18];
    for (int i = 0; i < 18; ++i) P[i] = (const float*)d_in[pb + i];

    float* out   = (float*)d_out;
    float* out_g = out;                               // [64, 256]
    float* out_n = out + (size_t)GG * HH;             // [20000, 256]
    float* out_e = out_n + (size_t)NNODE * HH;        // [320000, 256]

    cudaFuncSetAttribute(ffn_kernel, cudaFuncAttributeMaxDynamicSharedMemorySize, SMEM_BYTES);

    // tf32-round weights: node_w1, node_w2, glob_w1, glob_w2, edge_w1, edge_w2
    prep_kernel<<<3072, 256>>>(P[2], P[4], P[8], P[10], P[14], P[16]);

    // global features = segment mean of node features
    seg_mean_kernel<<<GG, HH>>>(nodef, batch, NNODE);

    // global readout (reads g_gf)
    ffn_kernel<<<1, THREADS, SMEM_BYTES>>>(
        nullptr, (long)GG, P[6], P[7], 2 * 131072, P[9], P[11], out_g, 1);

    // node readout
    ffn_kernel<<<(NNODE + TM - 1) / TM, THREADS, SMEM_BYTES>>>(
        nodef, (long)NNODE, P[0], P[1], 0, P[3], P[5], out_n, 0);

    // edge readout (viewed as [320000, 256])
    ffn_kernel<<<NEDGE / TM, THREADS, SMEM_BYTES>>>(
        edgef, (long)NEDGE, P[12], P[13], 4 * 131072, P[15], P[17], out_e, 0);
}

// round 8
// speedup vs baseline: 1.4617x; 1.4617x over previous
#include <cuda_runtime.h>
#include <cuda_fp16.h>
#include <cstdint>

#define HH 256
#define H2 512
#define GG 64
#define NNODE 20000
#define NEDGE 320000
#define TM 64
#define THREADS 256

#define ALDH 264                        // halves per A row
#define HLDH 520                        // halves per H row
#define WROW 24                         // halves per weight-tile row (16 data + 8 pad)
#define WTILE_BYTES (128 * WROW * 2)    // 6144
#define A_OFF 0
#define H_OFF (TM * ALDH * 2)           // 33792
#define W_OFF (H_OFF + TM * HLDH * 2)   // 100352
#define SMEM_BYTES (W_OFF + 2 * WTILE_BYTES)   // 112640  (x2 CTAs = 220KB/SM)

// fp16 weights, pre-transposed to k-major: per readout [w1t: 512n x 256k][w2t: 256n x 512k]
__device__ __align__(16) __half g_w[3 * 262144];
__device__ __align__(16) float  g_gf[GG * HH];

// ---------- helpers ----------
__device__ __forceinline__ float gelu_fast(float x) {
    float u = x * (0.7978845608028654f + 0.035677408136300125f * x * x);
    float t;
    asm("tanh.approx.f32 %0, %1;" : "=f"(t) : "f"(u));
    return 0.5f * x * (1.0f + t);
}

__device__ __forceinline__ void hmma(float* c, const unsigned* a, unsigned b0, unsigned b1) {
    asm volatile(
        "mma.sync.aligned.m16n8k16.row.col.f32.f16.f16.f32 "
        "{%0,%1,%2,%3}, {%4,%5,%6,%7}, {%8,%9}, {%0,%1,%2,%3};\n"
        : "+f"(c[0]), "+f"(c[1]), "+f"(c[2]), "+f"(c[3])
        : "r"(a[0]), "r"(a[1]), "r"(a[2]), "r"(a[3]), "r"(b0), "r"(b1));
}

#define CP_COMMIT asm volatile("cp.async.commit_group;\n")
#define CP_WAIT1  asm volatile("cp.async.wait_group 1;\n")
#define CP_WAIT0  asm volatile("cp.async.wait_group 0;\n")

// copy one [128n x 16k] fp16 weight tile into ring buffer `buf` (1 cp.async / thread)
__device__ __forceinline__ void copy_tile(char* smem, int buf, const __half* __restrict__ src,
                                          int ldk) {
    unsigned sb = (unsigned)__cvta_generic_to_shared(smem + W_OFF + buf * WTILE_BYTES);
    int row = threadIdx.x >> 1, part = threadIdx.x & 1;
    asm volatile("cp.async.cg.shared.global [%0], [%1], 16;\n"
                 ::"r"(sb + row * (WROW * 2) + part * 16),
                   "l"(src + (size_t)row * ldk + part * 8));
}

// ---------- prep: fp16 + transpose weights to k-major ----------
__global__ void prep_kernel(const float* __restrict__ n1, const float* __restrict__ n2,
                            const float* __restrict__ g1, const float* __restrict__ g2,
                            const float* __restrict__ e1, const float* __restrict__ e2) {
    int idx = blockIdx.x * blockDim.x + threadIdx.x;   // < 786432
    int rid = idx >> 18;
    int r   = idx & 262143;
    const float* w1 = (rid == 0) ? n1 : (rid == 1) ? g1 : e1;
    const float* w2 = (rid == 0) ? n2 : (rid == 1) ? g2 : e2;
    float v;
    if (r < 131072) { int n = r >> 8, k = r & 255; v = w1[(size_t)k * H2 + n]; }
    else            { int q = r - 131072; int n = q >> 9, k = q & 511; v = w2[(size_t)k * HH + n]; }
    g_w[idx] = __float2half_rn(v);
}

// ---------- segment mean (node_batch sorted) ----------
__global__ void seg_mean_kernel(const float* __restrict__ nf, const int* __restrict__ batch, int n) {
    int gid = blockIdx.x;
    int lo, hi;
    { int a = 0, b = n;  while (a < b) { int m = (a + b) >> 1; if (batch[m] <  gid) a = m + 1; else b = m; } lo = a; }
    { int a = lo, b = n; while (a < b) { int m = (a + b) >> 1; if (batch[m] <= gid) a = m + 1; else b = m; } hi = a; }
    int col = threadIdx.x;
    float s = 0.f;
    for (int r = lo; r < hi; ++r) s += nf[(size_t)r * HH + col];
    g_gf[gid * HH + col] = s / fmaxf((float)(hi - lo), 1.0f);
}

// ---------- one n-chunk of a GEMM: acc[64m x 128n] += A[64 x 16k*nkt] @ Wt^T ----------
__device__ __forceinline__ void gemm_chunk(char* smem, const __half* __restrict__ A_s, int lda,
                                           const __half* __restrict__ wt, int ldk, int nkt,
                                           float acc[2][4][4], int m0, int wn, int g, int tig) {
#pragma unroll
    for (int mt = 0; mt < 2; ++mt)
#pragma unroll
        for (int nt = 0; nt < 4; ++nt)
#pragma unroll
            for (int i = 0; i < 4; ++i) acc[mt][nt][i] = 0.f;

    copy_tile(smem, 0, wt, ldk);
    CP_COMMIT;
#pragma unroll 1
    for (int kt = 0; kt < nkt; ++kt) {
        int cur = kt & 1;
        if (kt + 1 < nkt) {
            copy_tile(smem, cur ^ 1, wt + (kt + 1) * 16, ldk);
            CP_COMMIT;
            CP_WAIT1;
        } else {
            CP_WAIT0;
        }
        __syncthreads();
        const __half* Ws = (const __half*)(smem + W_OFF + cur * WTILE_BYTES);
        int k = kt * 16;
        unsigned a[2][4];
#pragma unroll
        for (int mt = 0; mt < 2; ++mt) {
            int r = m0 + mt * 16 + g;
            a[mt][0] = *(const unsigned*)(A_s + (size_t)r * lda + k + 2 * tig);
            a[mt][1] = *(const unsigned*)(A_s + (size_t)(r + 8) * lda + k + 2 * tig);
            a[mt][2] = *(const unsigned*)(A_s + (size_t)r * lda + k + 2 * tig + 8);
            a[mt][3] = *(const unsigned*)(A_s + (size_t)(r + 8) * lda + k + 2 * tig + 8);
        }
#pragma unroll
        for (int nt = 0; nt < 4; ++nt) {
            int n = wn * 32 + nt * 8 + g;
            unsigned b0 = *(const unsigned*)(Ws + n * WROW + 2 * tig);
            unsigned b1 = *(const unsigned*)(Ws + n * WROW + 2 * tig + 8);
            hmma(acc[0][nt], a[0], b0, b1);
            hmma(acc[1][nt], a[1], b0, b1);
        }
        __syncthreads();
    }
}

// ---------- fused LN -> FFN -> residual (fp16 HMMA) ----------
__global__ void __launch_bounds__(THREADS, 2)
ffn_h(const float* __restrict__ Xp, long R,
      const float* __restrict__ gamma, const float* __restrict__ beta,
      int wbase, const float* __restrict__ b1, const float* __restrict__ b2,
      float* __restrict__ out, int use_gf) {
    extern __shared__ char smem[];
    const float*  X   = use_gf ? g_gf : Xp;
    const __half* w1t = g_w + wbase;
    const __half* w2t = w1t + 131072;
    __half* As = (__half*)(smem + A_OFF);
    __half* Hs = (__half*)(smem + H_OFF);

    int tid = threadIdx.x, warp = tid >> 5, lane = tid & 31;
    int g = lane >> 2, tig = lane & 3;
    int wm = warp >> 2, wn = warp & 3, m0 = wm * 32;
    long base = (long)blockIdx.x * TM;

    // ---- LayerNorm: warp per row, fully coalesced float4, store fp16 ----
    float4 gm0 = *(const float4*)(gamma + lane * 8);
    float4 gm1 = *(const float4*)(gamma + lane * 8 + 4);
    float4 bt0 = *(const float4*)(beta + lane * 8);
    float4 bt1 = *(const float4*)(beta + lane * 8 + 4);
#pragma unroll 1
    for (int rr = 0; rr < 8; ++rr) {
        int row = warp * 8 + rr;
        long gr = base + row;
        float4 v0 = make_float4(0.f, 0.f, 0.f, 0.f), v1 = v0;
        if (gr < R) {
            v0 = *(const float4*)(X + gr * HH + lane * 8);
            v1 = *(const float4*)(X + gr * HH + lane * 8 + 4);
        }
        float s = v0.x + v0.y + v0.z + v0.w + v1.x + v1.y + v1.z + v1.w;
        float q = v0.x * v0.x + v0.y * v0.y + v0.z * v0.z + v0.w * v0.w
                + v1.x * v1.x + v1.y * v1.y + v1.z * v1.z + v1.w * v1.w;
#pragma unroll
        for (int o = 16; o; o >>= 1) {
            s += __shfl_xor_sync(0xFFFFFFFFu, s, o);
            q += __shfl_xor_sync(0xFFFFFFFFu, q, o);
        }
        float mean = s * (1.0f / HH);
        float rstd = rsqrtf(q * (1.0f / HH) - mean * mean + 1e-5f);
        __half2 p0 = __floats2half2_rn((v0.x - mean) * rstd * gm0.x + bt0.x,
                                       (v0.y - mean) * rstd * gm0.y + bt0.y);
        __half2 p1 = __floats2half2_rn((v0.z - mean) * rstd * gm0.z + bt0.z,
                                       (v0.w - mean) * rstd * gm0.w + bt0.w);
        __half2 p2 = __floats2half2_rn((v1.x - mean) * rstd * gm1.x + bt1.x,
                                       (v1.y - mean) * rstd * gm1.y + bt1.y);
        __half2 p3 = __floats2half2_rn((v1.z - mean) * rstd * gm1.z + bt1.z,
                                       (v1.w - mean) * rstd * gm1.w + bt1.w);
        uint4 u;
        u.x = *(unsigned*)&p0; u.y = *(unsigned*)&p1;
        u.z = *(unsigned*)&p2; u.w = *(unsigned*)&p3;
        *(uint4*)(As + (size_t)row * ALDH + lane * 8) = u;
    }
    __syncthreads();

    float acc[2][4][4];

    // ---- GEMM1: H[64,512] = As @ w1, GELU -> Hs fp16 ----
#pragma unroll 1
    for (int nc = 0; nc < 4; ++nc) {
        gemm_chunk(smem, As, ALDH, w1t + (size_t)(nc * 128) * 256, 256, 16,
                   acc, m0, wn, g, tig);
#pragma unroll
        for (int nt = 0; nt < 4; ++nt) {
            int col = nc * 128 + wn * 32 + nt * 8 + 2 * tig;
            float2 bb = *(const float2*)(b1 + col);
#pragma unroll
            for (int mt = 0; mt < 2; ++mt) {
                int r = m0 + mt * 16 + g;
                *(__half2*)(Hs + (size_t)r * HLDH + col) =
                    __floats2half2_rn(gelu_fast(acc[mt][nt][0] + bb.x),
                                      gelu_fast(acc[mt][nt][1] + bb.y));
                *(__half2*)(Hs + (size_t)(r + 8) * HLDH + col) =
                    __floats2half2_rn(gelu_fast(acc[mt][nt][2] + bb.x),
                                      gelu_fast(acc[mt][nt][3] + bb.y));
            }
        }
    }
    __syncthreads();

    // ---- GEMM2: O[64,256] = Hs @ w2 + b2 + X ----
#pragma unroll 1
    for (int nc = 0; nc < 2; ++nc) {
        gemm_chunk(smem, Hs, HLDH, w2t + (size_t)(nc * 128) * 512, 512, 32,
                   acc, m0, wn, g, tig);
#pragma unroll
        for (int nt = 0; nt < 4; ++nt) {
            int col = nc * 128 + wn * 32 + nt * 8 + 2 * tig;
            float2 bb = *(const float2*)(b2 + col);
#pragma unroll
            for (int mt = 0; mt < 2; ++mt) {
                int r = m0 + mt * 16 + g;
                long gr0 = base + r, gr1 = gr0 + 8;
                if (gr0 < R) {
                    float2 x = *(const float2*)(X + gr0 * HH + col);
                    *(float2*)(out + gr0 * HH + col) =
                        make_float2(acc[mt][nt][0] + bb.x + x.x,
                                    acc[mt][nt][1] + bb.y + x.y);
                }
                if (gr1 < R) {
                    float2 x = *(const float2*)(X + gr1 * HH + col);
                    *(float2*)(out + gr1 * HH + col) =
                        make_float2(acc[mt][nt][2] + bb.x + x.x,
                                    acc[mt][nt][3] + bb.y + x.y);
                }
            }
        }
    }
}

// ---------- launch ----------
extern "C" void kernel_launch(void* const* d_in, const int* in_sizes, int n_in,
                              void* d_out, int out_size) {
    const float* nodef = (const float*)d_in[0];
    const float* edgef = (const float*)d_in[1];
    const int*   batch = (const int*)d_in[2];
    int pb = n_in - 18;
    const float* P[18];
    for (int i = 0; i < 18; ++i) P[i] = (const float*)d_in[pb + i];

    float* out   = (float*)d_out;
    float* out_g = out;
    float* out_n = out + (size_t)GG * HH;
    float* out_e = out_n + (size_t)NNODE * HH;

    cudaFuncSetAttribute(ffn_h, cudaFuncAttributeMaxDynamicSharedMemorySize, SMEM_BYTES);

    prep_kernel<<<3072, 256>>>(P[2], P[4], P[8], P[10], P[14], P[16]);
    seg_mean_kernel<<<GG, HH>>>(nodef, batch, NNODE);

    ffn_h<<<1, THREADS, SMEM_BYTES>>>(nullptr, (long)GG, P[6], P[7], 262144, P[9], P[11], out_g, 1);
    ffn_h<<<(NNODE + TM - 1) / TM, THREADS, SMEM_BYTES>>>(nodef, (long)NNODE, P[0], P[1], 0, P[3], P[5], out_n, 0);
    ffn_h<<<NEDGE / TM, THREADS, SMEM_BYTES>>>(edgef, (long)NEDGE, P[12], P[13], 524288, P[15], P[17], out_e, 0);
}

// round 9
// speedup vs baseline: 1.8502x; 1.2657x over previous
#include <cuda_runtime.h>
#include <cuda_fp16.h>
#include <cstdint>

#define HH 256
#define H2 512
#define GG 64
#define NNODE 20000
#define NEDGE 320000
#define THREADS 256

#define WP 264                    // pass-A W row halves (256 + 8 pad)
#define AP 264                    // A row halves
#define HP 520                    // pass-B row halves (512 + 8 pad)
#define A_WS_BYTES (256 * WP * 2) // 135168
#define A_AS_BYTES (64 * AP * 2)  // 33792
#define A_SMEM (A_WS_BYTES + 2 * A_AS_BYTES)  // 202752
#define B_WS_BYTES (128 * HP * 2) // 133120
#define B_HS_BYTES (64 * HP * 2)  // 66560
#define B_SMEM (B_WS_BYTES + B_HS_BYTES)      // 199680

// fp16 weights k-major: per readout [w1t: 512n x 256k][w2t: 256n x 512k]
__device__ __align__(16) __half g_w[3 * 262144];
__device__ __align__(16) float  g_gf[GG * HH];
__device__ __align__(16) __half g_a[(size_t)NEDGE * HH];   // LN(X) fp16
__device__ __align__(16) __half g_h[(size_t)NEDGE * H2];   // hidden fp16

// ---------- helpers ----------
__device__ __forceinline__ float gelu_fast(float x) {
    float u = x * (0.7978845608028654f + 0.035677408136300125f * x * x);
    float t;
    asm("tanh.approx.f32 %0, %1;" : "=f"(t) : "f"(u));
    return 0.5f * x * (1.0f + t);
}
__device__ __forceinline__ void hmma(float* c, const unsigned* a, unsigned b0, unsigned b1) {
    asm volatile(
        "mma.sync.aligned.m16n8k16.row.col.f32.f16.f16.f32 "
        "{%0,%1,%2,%3}, {%4,%5,%6,%7}, {%8,%9}, {%0,%1,%2,%3};\n"
        : "+f"(c[0]), "+f"(c[1]), "+f"(c[2]), "+f"(c[3])
        : "r"(a[0]), "r"(a[1]), "r"(a[2]), "r"(a[3]), "r"(b0), "r"(b1));
}
#define CP_COMMIT asm volatile("cp.async.commit_group;\n")
#define CP_WAIT1  asm volatile("cp.async.wait_group 1;\n")
#define CP_WAIT0  asm volatile("cp.async.wait_group 0;\n")
__device__ __forceinline__ void cpa(unsigned dst, const void* src) {
    asm volatile("cp.async.cg.shared.global [%0], [%1], 16;\n" ::"r"(dst), "l"(src));
}

// ---------- prep: fp16 + transpose weights to k-major ----------
__global__ void prep_kernel(const float* __restrict__ n1, const float* __restrict__ n2,
                            const float* __restrict__ g1, const float* __restrict__ g2,
                            const float* __restrict__ e1, const float* __restrict__ e2) {
    int idx = blockIdx.x * blockDim.x + threadIdx.x;
    int rid = idx >> 18;
    int r = idx & 262143;
    const float* w1 = (rid == 0) ? n1 : (rid == 1) ? g1 : e1;
    const float* w2 = (rid == 0) ? n2 : (rid == 1) ? g2 : e2;
    float v;
    if (r < 131072) { int n = r >> 8, k = r & 255; v = w1[(size_t)k * H2 + n]; }
    else { int q = r - 131072; int n = q >> 9, k = q & 511; v = w2[(size_t)k * HH + n]; }
    g_w[idx] = __float2half_rn(v);
}

// ---------- segment mean (node_batch sorted) ----------
__global__ void seg_mean_kernel(const float* __restrict__ nf, const int* __restrict__ batch, int n) {
    int gid = blockIdx.x;
    int lo, hi;
    { int a = 0, b = n;  while (a < b) { int m = (a + b) >> 1; if (batch[m] <  gid) a = m + 1; else b = m; } lo = a; }
    { int a = lo, b = n; while (a < b) { int m = (a + b) >> 1; if (batch[m] <= gid) a = m + 1; else b = m; } hi = a; }
    int col = threadIdx.x;
    float s = 0.f;
    for (int r = lo; r < hi; ++r) s += nf[(size_t)r * HH + col];
    g_gf[gid * HH + col] = s / fmaxf((float)(hi - lo), 1.0f);
}

// ---------- LN pass: X -> g_a fp16, one warp per row ----------
__global__ void ln_kernel(const float* __restrict__ Xp, long R,
                          const float* __restrict__ gamma, const float* __restrict__ beta,
                          int use_gf) {
    const float* X = use_gf ? g_gf : Xp;
    int warp = threadIdx.x >> 5, lane = threadIdx.x & 31;
    long row = (long)blockIdx.x * 8 + warp;
    if (row >= R) return;
    float4 v0 = *(const float4*)(X + row * HH + lane * 8);
    float4 v1 = *(const float4*)(X + row * HH + lane * 8 + 4);
    float s = v0.x + v0.y + v0.z + v0.w + v1.x + v1.y + v1.z + v1.w;
    float q = v0.x * v0.x + v0.y * v0.y + v0.z * v0.z + v0.w * v0.w
            + v1.x * v1.x + v1.y * v1.y + v1.z * v1.z + v1.w * v1.w;
#pragma unroll
    for (int o = 16; o; o >>= 1) {
        s += __shfl_xor_sync(0xFFFFFFFFu, s, o);
        q += __shfl_xor_sync(0xFFFFFFFFu, q, o);
    }
    float mean = s * (1.0f / HH);
    float rstd = rsqrtf(q * (1.0f / HH) - mean * mean + 1e-5f);
    float4 gm0 = *(const float4*)(gamma + lane * 8);
    float4 gm1 = *(const float4*)(gamma + lane * 8 + 4);
    float4 bt0 = *(const float4*)(beta + lane * 8);
    float4 bt1 = *(const float4*)(beta + lane * 8 + 4);
    __half2 p0 = __floats2half2_rn((v0.x - mean) * rstd * gm0.x + bt0.x, (v0.y - mean) * rstd * gm0.y + bt0.y);
    __half2 p1 = __floats2half2_rn((v0.z - mean) * rstd * gm0.z + bt0.z, (v0.w - mean) * rstd * gm0.w + bt0.w);
    __half2 p2 = __floats2half2_rn((v1.x - mean) * rstd * gm1.x + bt1.x, (v1.y - mean) * rstd * gm1.y + bt1.y);
    __half2 p3 = __floats2half2_rn((v1.z - mean) * rstd * gm1.z + bt1.z, (v1.w - mean) * rstd * gm1.w + bt1.w);
    uint4 u;
    u.x = *(unsigned*)&p0; u.y = *(unsigned*)&p1; u.z = *(unsigned*)&p2; u.w = *(unsigned*)&p3;
    *(uint4*)(g_a + row * HH + lane * 8) = u;
}

// ---------- pass A: H = gelu(A @ w1half + b1) -> g_h, weight-stationary ----------
__global__ void __launch_bounds__(THREADS, 1)
gemm1_kernel(long R, int ntiles, int wbase, const float* __restrict__ bias1) {
    extern __shared__ char smem[];
    __half* Ws  = (__half*)smem;                       // 256n x WP
    __half* As0 = (__half*)(smem + A_WS_BYTES);        // 2 x 64 x AP
    int h = blockIdx.x, tid = threadIdx.x;
    int warp = tid >> 5, lane = tid & 31, g = lane >> 2, tig = lane & 3;
    int wm = warp >> 2, wn = warp & 3, m0 = wm * 32;
    unsigned ws_s = (unsigned)__cvta_generic_to_shared(Ws);
    unsigned as_s = (unsigned)__cvta_generic_to_shared(As0);

    {   // weight half load (once), overlapped with first A prefetch
        const __half* src = g_w + wbase + (size_t)h * 256 * 256;
#pragma unroll
        for (int it = 0; it < 32; ++it) {
            int idx = tid + it * THREADS;
            int row = idx >> 5, seg = idx & 31;
            cpa(ws_s + row * (WP * 2) + seg * 16, src + row * 256 + seg * 8);
        }
        CP_COMMIT;
    }
    long t = blockIdx.y;
    if (t < ntiles) {
#pragma unroll
        for (int it = 0; it < 8; ++it) {
            int idx = tid + it * THREADS;
            int row = idx >> 5, seg = idx & 31;
            cpa(as_s + row * (AP * 2) + seg * 16, g_a + ((size_t)t * 64 + row) * HH + seg * 8);
        }
        CP_COMMIT;
    }
    int buf = 0;
    for (; t < ntiles; t += gridDim.y, buf ^= 1) {
        long tn = t + gridDim.y;
        if (tn < ntiles) {
            unsigned db = as_s + (buf ^ 1) * A_AS_BYTES;
#pragma unroll
            for (int it = 0; it < 8; ++it) {
                int idx = tid + it * THREADS;
                int row = idx >> 5, seg = idx & 31;
                cpa(db + row * (AP * 2) + seg * 16, g_a + ((size_t)tn * 64 + row) * HH + seg * 8);
            }
            CP_COMMIT; CP_WAIT1;
        } else { CP_WAIT0; }
        __syncthreads();

        const __half* As = As0 + buf * (A_AS_BYTES / 2);
        float acc[2][8][4];
#pragma unroll
        for (int mt = 0; mt < 2; ++mt)
#pragma unroll
            for (int nt = 0; nt < 8; ++nt)
#pragma unroll
                for (int i = 0; i < 4; ++i) acc[mt][nt][i] = 0.f;
#pragma unroll 4
        for (int kt = 0; kt < 16; ++kt) {
            int k = kt * 16;
            unsigned a[2][4];
#pragma unroll
            for (int mt = 0; mt < 2; ++mt) {
                int r = m0 + mt * 16 + g;
                a[mt][0] = *(const unsigned*)(As + r * AP + k + 2 * tig);
                a[mt][1] = *(const unsigned*)(As + (r + 8) * AP + k + 2 * tig);
                a[mt][2] = *(const unsigned*)(As + r * AP + k + 8 + 2 * tig);
                a[mt][3] = *(const unsigned*)(As + (r + 8) * AP + k + 8 + 2 * tig);
            }
#pragma unroll
            for (int nt = 0; nt < 8; ++nt) {
                int n = wn * 64 + nt * 8 + g;
                unsigned b0 = *(const unsigned*)(Ws + n * WP + k + 2 * tig);
                unsigned b1 = *(const unsigned*)(Ws + n * WP + k + 8 + 2 * tig);
                hmma(acc[0][nt], a[0], b0, b1);
                hmma(acc[1][nt], a[1], b0, b1);
            }
        }
        __syncthreads();
        // GELU stage into As[buf]
        __half* Hst = (__half*)As;
#pragma unroll
        for (int nt = 0; nt < 8; ++nt) {
            int col = wn * 64 + nt * 8 + 2 * tig;
            float2 bb = *(const float2*)(bias1 + h * 256 + col);
#pragma unroll
            for (int mt = 0; mt < 2; ++mt) {
                int r = m0 + mt * 16 + g;
                *(__half2*)(Hst + r * AP + col) =
                    __floats2half2_rn(gelu_fast(acc[mt][nt][0] + bb.x),
                                      gelu_fast(acc[mt][nt][1] + bb.y));
                *(__half2*)(Hst + (r + 8) * AP + col) =
                    __floats2half2_rn(gelu_fast(acc[mt][nt][2] + bb.x),
                                      gelu_fast(acc[mt][nt][3] + bb.y));
            }
        }
        __syncthreads();
        long base = t * 64;
#pragma unroll
        for (int it = 0; it < 8; ++it) {
            int idx = tid + it * THREADS;
            int row = idx >> 5, seg = idx & 31;
            if (base + row < R) {
                uint4 u = *(const uint4*)(Hst + row * AP + seg * 8);
                *(uint4*)(g_h + (base + row) * H2 + h * 256 + seg * 8) = u;
            }
        }
        __syncthreads();
    }
}

// ---------- pass B: out = H @ w2half + b2 + X, weight-stationary ----------
__global__ void __launch_bounds__(THREADS, 1)
gemm2_kernel(const float* __restrict__ Xp, long R, int ntiles, int wbase,
             const float* __restrict__ bias2, float* __restrict__ out, int use_gf) {
    extern __shared__ char smem[];
    __half* Ws = (__half*)smem;                  // 128n x HP
    __half* Hs = (__half*)(smem + B_WS_BYTES);   // 64 x HP
    const float* X = use_gf ? g_gf : Xp;
    int h = blockIdx.x, tid = threadIdx.x;
    int warp = tid >> 5, lane = tid & 31, g = lane >> 2, tig = lane & 3;
    int wm = warp >> 2, wn = warp & 3, m0 = wm * 32;
    unsigned ws_s = (unsigned)__cvta_generic_to_shared(Ws);
    unsigned hs_s = (unsigned)__cvta_generic_to_shared(Hs);

    {   // w2 half load (once)
        const __half* src = g_w + wbase + 131072 + (size_t)h * 128 * 512;
#pragma unroll
        for (int it = 0; it < 32; ++it) {
            int idx = tid + it * THREADS;
            int row = idx >> 6, seg = idx & 63;
            cpa(ws_s + row * (HP * 2) + seg * 16, src + row * 512 + seg * 8);
        }
        CP_COMMIT;
    }
    for (long t = blockIdx.y; t < ntiles; t += gridDim.y) {
        long base = t * 64;
#pragma unroll
        for (int it = 0; it < 16; ++it) {
            int idx = tid + it * THREADS;
            int row = idx >> 6, seg = idx & 63;
            cpa(hs_s + row * (HP * 2) + seg * 16, g_h + (base + row) * H2 + seg * 8);
        }
        CP_COMMIT; CP_WAIT0;
        __syncthreads();

        float acc[2][4][4];
#pragma unroll
        for (int mt = 0; mt < 2; ++mt)
#pragma unroll
            for (int nt = 0; nt < 4; ++nt)
#pragma unroll
                for (int i = 0; i < 4; ++i) acc[mt][nt][i] = 0.f;
#pragma unroll 4
        for (int kt = 0; kt < 32; ++kt) {
            int k = kt * 16;
            unsigned a[2][4];
#pragma unroll
            for (int mt = 0; mt < 2; ++mt) {
                int r = m0 + mt * 16 + g;
                a[mt][0] = *(const unsigned*)(Hs + r * HP + k + 2 * tig);
                a[mt][1] = *(const unsigned*)(Hs + (r + 8) * HP + k + 2 * tig);
                a[mt][2] = *(const unsigned*)(Hs + r * HP + k + 8 + 2 * tig);
                a[mt][3] = *(const unsigned*)(Hs + (r + 8) * HP + k + 8 + 2 * tig);
            }
#pragma unroll
            for (int nt = 0; nt < 4; ++nt) {
                int n = wn * 32 + nt * 8 + g;
                unsigned b0 = *(const unsigned*)(Ws + n * HP + k + 2 * tig);
                unsigned b1 = *(const unsigned*)(Ws + n * HP + k + 8 + 2 * tig);
                hmma(acc[0][nt], a[0], b0, b1);
                hmma(acc[1][nt], a[1], b0, b1);
            }
        }
        // epilogue
#pragma unroll
        for (int nt = 0; nt < 4; ++nt) {
            int col = h * 128 + wn * 32 + nt * 8 + 2 * tig;
            float2 bb = *(const float2*)(bias2 + col);
#pragma unroll
            for (int mt = 0; mt < 2; ++mt) {
                int r = m0 + mt * 16 + g;
                long gr0 = base + r, gr1 = gr0 + 8;
                if (gr0 < R) {
                    float2 x = *(const float2*)(X + gr0 * HH + col);
                    *(float2*)(out + gr0 * HH + col) =
                        make_float2(acc[mt][nt][0] + bb.x + x.x, acc[mt][nt][1] + bb.y + x.y);
                }
                if (gr1 < R) {
                    float2 x = *(const float2*)(X + gr1 * HH + col);
                    *(float2*)(out + gr1 * HH + col) =
                        make_float2(acc[mt][nt][2] + bb.x + x.x, acc[mt][nt][3] + bb.y + x.y);
                }
            }
        }
        __syncthreads();
    }
}

// ---------- launch ----------
extern "C" void kernel_launch(void* const* d_in, const int* in_sizes, int n_in,
                              void* d_out, int out_size) {
    const float* nodef = (const float*)d_in[0];
    const float* edgef = (const float*)d_in[1];
    const int*   batch = (const int*)d_in[2];
    int pb = n_in - 18;
    const float* P[18];
    for (int i = 0; i < 18; ++i) P[i] = (const float*)d_in[pb + i];

    float* out   = (float*)d_out;
    float* out_g = out;
    float* out_n = out + (size_t)GG * HH;
    float* out_e = out_n + (size_t)NNODE * HH;

    cudaFuncSetAttribute(gemm1_kernel, cudaFuncAttributeMaxDynamicSharedMemorySize, A_SMEM);
    cudaFuncSetAttribute(gemm2_kernel, cudaFuncAttributeMaxDynamicSharedMemorySize, B_SMEM);

    prep_kernel<<<3072, 256>>>(P[2], P[4], P[8], P[10], P[14], P[16]);
    seg_mean_kernel<<<GG, HH>>>(nodef, batch, NNODE);

    // node
    ln_kernel<<<(NNODE + 7) / 8, 256>>>(nodef, NNODE, P[0], P[1], 0);
    gemm1_kernel<<<dim3(2, 74), THREADS, A_SMEM>>>(NNODE, 313, 0, P[3]);
    gemm2_kernel<<<dim3(2, 74), THREADS, B_SMEM>>>(nodef, NNODE, 313, 0, P[5], out_n, 0);
    // global
    ln_kernel<<<8, 256>>>(nullptr, GG, P[6], P[7], 1);
    gemm1_kernel<<<dim3(2, 1), THREADS, A_SMEM>>>(GG, 1, 262144, P[9]);
    gemm2_kernel<<<dim3(2, 1), THREADS, B_SMEM>>>(nullptr, GG, 1, 262144, P[11], out_g, 1);
    // edge
    ln_kernel<<<NEDGE / 8, 256>>>(edgef, NEDGE, P[12], P[13], 0);
    gemm1_kernel<<<dim3(2, 74), THREADS, A_SMEM>>>(NEDGE, 5000, 524288, P[15]);
    gemm2_kernel<<<dim3(2, 74), THREADS, B_SMEM>>>(edgef, NEDGE, 5000, 524288, P[17], out_e, 0);
}